// round 13
// baseline (speedup 1.0000x reference)
#include <cuda_runtime.h>
#include <cuda_bf16.h>
#include <cstdint>

// BankedLinear: B=2, T=256, K=2, IN=OUT=512, NB=64
#define NB       64
#define IN_DIM   512
#define OUT_DIM  512
#define KSEL     2
#define NENT     1024
#define O_SPLIT  4
#define O_CHUNK  128                 // outs per CTA (16 per warp)
#define K_SPLIT  2
#define KRANGE   (IN_DIM / K_SPLIT)  // 256 k rows per CTA
#define NKS      (KRANGE / 16)       // 16 k16-steps
#define MTOK     32                  // token tile: 2 m-tiles of 16
#define NTHR     256                 // 8 warps
#define NSTAGE   4                   // per-warp W ring depth
#define WPITCH   20                  // floats per W row (bank-conflict-free)
#define WSTG_B   (16 * WPITCH * 4)   // 1280 B per stage per warp
#define WRING_B  (NSTAGE * WSTG_B)   // 5120 B per warp

// dynamic smem layout
#define OFF_XH   0                          // 16 KB: A-frag bf16x2 hi
#define OFF_XL   16384                      // 16 KB: A-frag bf16x2 lo
#define OFF_WS   32768                      // 8 warps x 5120 = 40960
#define OFF_ENT  (OFF_WS + 8 * WRING_B)     // 73728: 1024 u16
#define OFF_CNT  (OFF_ENT + 2048)           // 75776
#define SMEM_BYTES (OFF_CNT + 16)           // 75792  (x3 CTAs = 227 KB/SM)

__global__ void zero_out_kernel(float4* __restrict__ out, int n4) {
    int i = blockIdx.x * blockDim.x + threadIdx.x;
    if (i < n4) out[i] = make_float4(0.f, 0.f, 0.f, 0.f);
}

__device__ __forceinline__ void cp_async16(void* dst, const void* src) {
    unsigned d = (unsigned)__cvta_generic_to_shared(dst);
    asm volatile("cp.async.cg.shared.global [%0], [%1], 16;\n" :: "r"(d), "l"(src));
}
#define CP_COMMIT() asm volatile("cp.async.commit_group;\n" ::)
#define CP_WAIT3()  asm volatile("cp.async.wait_group 3;\n" ::)
#define CP_WAIT0()  asm volatile("cp.async.wait_group 0;\n" ::)

// bf16x2 pack: low half <- lo, high half <- hi (single cvt instruction)
__device__ __forceinline__ uint32_t cvt2(float hi, float lo) {
    uint32_t r;
    asm("cvt.rn.bf16x2.f32 %0, %1, %2;" : "=r"(r) : "f"(hi), "f"(lo));
    return r;
}
// split a float pair into hi/lo bf16x2 regs: 6 ops instead of 8
__device__ __forceinline__ void split_pair(float f0, float f1,
                                           uint32_t& h, uint32_t& l) {
    h = cvt2(f1, f0);
    float h0 = __uint_as_float(h << 16);
    float h1 = __uint_as_float(h & 0xFFFF0000u);
    l = cvt2(f1 - h1, f0 - h0);
}
__device__ __forceinline__ void mma16(float* c, const uint32_t* a, const uint32_t* b) {
    asm volatile(
        "mma.sync.aligned.m16n8k16.row.col.f32.bf16.bf16.f32 "
        "{%0,%1,%2,%3}, {%4,%5,%6,%7}, {%8,%9}, {%0,%1,%2,%3};"
        : "+f"(c[0]), "+f"(c[1]), "+f"(c[2]), "+f"(c[3])
        : "r"(a[0]), "r"(a[1]), "r"(a[2]), "r"(a[3]), "r"(b[0]), "r"(b[1]));
}

__global__ __launch_bounds__(NTHR, 3)
void banked_linear_bf16(const float* __restrict__ x,     // [BT, IN]
                        const int*   __restrict__ sel,   // [BT, K]
                        const float* __restrict__ prob,  // [BT, K]
                        const float* __restrict__ W,     // [NB, IN, OUT]
                        const float* __restrict__ bias,  // [NB, OUT]
                        float*       __restrict__ out)   // [BT, OUT]
{
    extern __shared__ __align__(16) char dsm[];
    uint32_t*       xs_h  = (uint32_t*)(dsm + OFF_XH);
    uint32_t*       xs_l  = (uint32_t*)(dsm + OFF_XL);
    unsigned short* s_ent = (unsigned short*)(dsm + OFF_ENT);
    int*            s_cnt = (int*)(dsm + OFF_CNT);

    const int bank  = blockIdx.x;
    const int oBase = blockIdx.y * O_CHUNK;
    const int kOff  = blockIdx.z * KRANGE;
    const int tid   = threadIdx.x;
    const int warp  = tid >> 5;
    const int lane  = tid & 31;
    const int gr    = lane >> 2;
    const int tg    = lane & 3;
    const int wcol  = warp * 16;

    char*  wring  = dsm + OFF_WS + warp * WRING_B;   // warp-private W ring
    float* wringf = (float*)wring;

    if (tid == 0) *s_cnt = 0;
    __syncthreads();

    for (int e = tid; e < NENT; e += NTHR) {
        if (sel[e] == bank) {
            int pos = atomicAdd(s_cnt, 1);
            s_ent[pos] = (unsigned short)e;
        }
    }
    __syncthreads();
    const int count = *s_cnt;
    if (count == 0) return;

    // Warp's 16-col W slice, rows kOff..kOff+KRANGE.
    const float* Ww = W + (size_t)bank * IN_DIM * OUT_DIM
                        + (size_t)kOff * OUT_DIM + oBase + wcol;
    float2 bb[2];
    if (blockIdx.z == 0) {
        bb[0] = *(const float2*)(bias + (size_t)bank * OUT_DIM + oBase + wcol + tg * 2);
        bb[1] = *(const float2*)(bias + (size_t)bank * OUT_DIM + oBase + wcol + 8 + tg * 2);
    } else {
        bb[0] = make_float2(0.f, 0.f);
        bb[1] = make_float2(0.f, 0.f);
    }

    for (int tt = 0; tt < count; tt += MTOK) {
        // ── prologue: W ring stages 0..2 ──
        #pragma unroll
        for (int s = 0; s < NSTAGE - 1; s++) {
            #pragma unroll
            for (int q = 0; q < 2; q++) {
                int idx = lane * 2 + q;
                int row = idx >> 2, c16 = idx & 3;
                cp_async16(wring + s * WSTG_B + row * (WPITCH * 4) + c16 * 16,
                           Ww + (size_t)(s * 16 + row) * OUT_DIM + c16 * 4);
            }
            CP_COMMIT();
        }

        // ── stage x: prescale, bf16 hi/lo split (packed cvt), A-frag layout ──
        #pragma unroll
        for (int it = 0; it < 8; it++) {
            int j = tid + it * NTHR;      // 2048 = 32 slots x 64 k4-groups
            int t = j & 31;
            int q = j >> 5;               // k4-group within KRANGE
            int e = tt + t;
            float4 v = make_float4(0.f, 0.f, 0.f, 0.f);
            float  p = 0.f;
            if (e < count) {
                int ge = s_ent[e];
                p = prob[ge];
                v = *(const float4*)(x + (size_t)(ge >> 1) * IN_DIM + kOff + q * 4);
            }
            uint32_t hA, lA, hB, lB;
            split_pair(v.x * p, v.y * p, hA, lA);
            split_pair(v.z * p, v.w * p, hB, lB);
            int trow = t & 15, mt = t >> 4;
            int grs = trow & 7, jb = trow >> 3;
            int ks = q >> 2;
            int kk = (q & 3) * 4;
            int tgA = (kk >> 1) & 3,       jA = jb + 2 * (kk >> 3);
            int tgB = ((kk + 2) >> 1) & 3, jB = jb + 2 * ((kk + 2) >> 3);
            int base = ks * 256 + mt * 128;
            int wA = base + (grs * 4 + tgA) * 4 + jA;
            int wB = base + (grs * 4 + tgB) * 4 + jB;
            xs_h[wA] = hA;  xs_h[wB] = hB;
            xs_l[wA] = lA;  xs_l[wB] = lB;
        }
        __syncthreads();   // xs visible; warps free-run from here

        float c[2][2][4];
        #pragma unroll
        for (int mt = 0; mt < 2; mt++)
            #pragma unroll
            for (int nt = 0; nt < 2; nt++)
                #pragma unroll
                for (int i = 0; i < 4; i++) c[mt][nt][i] = 0.f;

        // ── mainloop: barrier-free, warp-private W ring ──
        for (int ks = 0; ks < NKS; ks++) {
            int nks = ks + NSTAGE - 1;
            if (nks < NKS) {
                int slot = nks & (NSTAGE - 1);
                #pragma unroll
                for (int q = 0; q < 2; q++) {
                    int idx = lane * 2 + q;
                    int row = idx >> 2, c16 = idx & 3;
                    cp_async16(wring + slot * WSTG_B + row * (WPITCH * 4) + c16 * 16,
                               Ww + (size_t)(nks * 16 + row) * OUT_DIM + c16 * 4);
                }
            }
            CP_COMMIT();         // commit even when empty: keeps group counts aligned
            CP_WAIT3();          // stage ks ready (warp-local)

            const float* wsf = wringf + (ks & (NSTAGE - 1)) * (16 * WPITCH);

            // B fragments: rows 2tg,2tg+1,2tg+8,2tg+9; cols nt*8+gr
            uint32_t bh[2][2], bl[2][2];
            #pragma unroll
            for (int nt = 0; nt < 2; nt++) {
                int cc = nt * 8 + gr;
                float w0 = wsf[(2 * tg) * WPITCH + cc];
                float w1 = wsf[(2 * tg + 1) * WPITCH + cc];
                float w2 = wsf[(2 * tg + 8) * WPITCH + cc];
                float w3 = wsf[(2 * tg + 9) * WPITCH + cc];
                split_pair(w0, w1, bh[nt][0], bl[nt][0]);
                split_pair(w2, w3, bh[nt][1], bl[nt][1]);
            }

            #pragma unroll
            for (int mt = 0; mt < 2; mt++) {
                uint32_t ah[4], al[4];
                *(uint4*)ah = *(const uint4*)&xs_h[ks * 256 + mt * 128 + lane * 4];
                *(uint4*)al = *(const uint4*)&xs_l[ks * 256 + mt * 128 + lane * 4];
                #pragma unroll
                for (int nt = 0; nt < 2; nt++) {
                    mma16(c[mt][nt], ah, bh[nt]);   // hi*hi
                    mma16(c[mt][nt], al, bh[nt]);   // lo*hi
                    mma16(c[mt][nt], ah, bl[nt]);   // hi*lo
                }
            }
        }
        CP_WAIT0();   // retire stragglers before ring/xs reuse

        // ── epilogue: vector red (acc prob-prescaled; p*bias from z==0 only) ──
        #pragma unroll
        for (int mt = 0; mt < 2; mt++) {
            #pragma unroll
            for (int nt = 0; nt < 2; nt++) {
                int colb = oBase + wcol + nt * 8 + tg * 2;
                int s0 = tt + mt * 16 + gr;
                if (s0 < count) {
                    int ge = s_ent[s0];
                    float p = prob[ge];
                    float* po = out + (size_t)(ge >> 1) * OUT_DIM + colb;
                    float v0 = c[mt][nt][0] + p * bb[nt].x;
                    float v1 = c[mt][nt][1] + p * bb[nt].y;
                    asm volatile("red.global.add.v2.f32 [%0], {%1, %2};"
                                 :: "l"(po), "f"(v0), "f"(v1) : "memory");
                }
                int s1 = tt + mt * 16 + gr + 8;
                if (s1 < count) {
                    int ge = s_ent[s1];
                    float p = prob[ge];
                    float* po = out + (size_t)(ge >> 1) * OUT_DIM + colb;
                    float v0 = c[mt][nt][2] + p * bb[nt].x;
                    float v1 = c[mt][nt][3] + p * bb[nt].y;
                    asm volatile("red.global.add.v2.f32 [%0], {%1, %2};"
                                 :: "l"(po), "f"(v0), "f"(v1) : "memory");
                }
            }
        }
        __syncthreads();   // xs reuse barrier (rare multi-tile case)
    }
}

extern "C" void kernel_launch(void* const* d_in, const int* in_sizes, int n_in,
                              void* d_out, int out_size) {
    const float* x    = (const float*)d_in[0];
    const int*   sel  = (const int*)  d_in[1];
    const float* prob = (const float*)d_in[2];
    const float* W    = (const float*)d_in[3];
    const float* bias = (const float*)d_in[4];
    float* out = (float*)d_out;

    cudaFuncSetAttribute(banked_linear_bf16,
                         cudaFuncAttributeMaxDynamicSharedMemorySize, SMEM_BYTES);

    int n4 = out_size / 4;
    zero_out_kernel<<<(n4 + 255) / 256, 256>>>((float4*)out, n4);

    dim3 grid(NB, O_SPLIT, K_SPLIT);
    banked_linear_bf16<<<grid, NTHR, SMEM_BYTES>>>(x, sel, prob, W, bias, out);
}

// round 14
// speedup vs baseline: 1.0438x; 1.0438x over previous
#include <cuda_runtime.h>
#include <cuda_bf16.h>
#include <cstdint>

// BankedLinear: B=2, T=256, K=2, IN=OUT=512, NB=64
#define NB       64
#define IN_DIM   512
#define OUT_DIM  512
#define KSEL     2
#define NENT     1024
#define O_SPLIT  4
#define O_CHUNK  128                 // outs per CTA (16 per warp)
#define NKS      32                  // k16-steps (full K=512)
#define MTOK     32                  // token tile: 2 m-tiles of 16
#define NTHR     256                 // 8 warps
#define NSTAGE   4                   // per-warp W ring depth
#define WPITCH   20                  // floats per W row (bank-conflict-free)
#define WSTG_B   (16 * WPITCH * 4)   // 1280 B per stage per warp
#define WRING_B  (NSTAGE * WSTG_B)   // 5120 B per warp

// dynamic smem layout
#define OFF_XH   0                          // 32 KB: A-frag bf16x2 hi
#define OFF_XL   32768                      // 32 KB: A-frag bf16x2 lo
#define OFF_WS   65536                      // 8 warps x 5120 = 40960
#define OFF_ENT  (OFF_WS + 8 * WRING_B)     // 106496: 1024 u16
#define OFF_CNT  (OFF_ENT + 2048)           // 108544
#define SMEM_BYTES (OFF_CNT + 16)           // 108560

__global__ void zero_out_kernel(float4* __restrict__ out, int n4) {
    int i = blockIdx.x * blockDim.x + threadIdx.x;
    if (i < n4) out[i] = make_float4(0.f, 0.f, 0.f, 0.f);
}

// cp.async with L2 evict_last policy: keep W resident in L2 across graph replays.
__device__ __forceinline__ void cp_async16_l2(void* dst, const void* src, uint64_t pol) {
    unsigned d = (unsigned)__cvta_generic_to_shared(dst);
    asm volatile("cp.async.cg.shared.global.L2::cache_hint [%0], [%1], 16, %2;\n"
                 :: "r"(d), "l"(src), "l"(pol));
}
#define CP_COMMIT() asm volatile("cp.async.commit_group;\n" ::)
#define CP_WAIT3()  asm volatile("cp.async.wait_group 3;\n" ::)
#define CP_WAIT0()  asm volatile("cp.async.wait_group 0;\n" ::)

__device__ __forceinline__ uint32_t pack2(__nv_bfloat16 lo, __nv_bfloat16 hi) {
    uint32_t u;
    asm("mov.b32 %0, {%1, %2};" : "=r"(u)
        : "h"(__bfloat16_as_ushort(lo)), "h"(__bfloat16_as_ushort(hi)));
    return u;
}
__device__ __forceinline__ void splitbf(float f, __nv_bfloat16& h, __nv_bfloat16& l) {
    h = __float2bfloat16_rn(f);
    l = __float2bfloat16_rn(f - __bfloat162float(h));
}
__device__ __forceinline__ void mma16(float* c, const uint32_t* a, const uint32_t* b) {
    asm volatile(
        "mma.sync.aligned.m16n8k16.row.col.f32.bf16.bf16.f32 "
        "{%0,%1,%2,%3}, {%4,%5,%6,%7}, {%8,%9}, {%0,%1,%2,%3};"
        : "+f"(c[0]), "+f"(c[1]), "+f"(c[2]), "+f"(c[3])
        : "r"(a[0]), "r"(a[1]), "r"(a[2]), "r"(a[3]), "r"(b[0]), "r"(b[1]));
}

__global__ __launch_bounds__(NTHR, 2)
void banked_linear_bf16(const float* __restrict__ x,     // [BT, IN]
                        const int*   __restrict__ sel,   // [BT, K]
                        const float* __restrict__ prob,  // [BT, K]
                        const float* __restrict__ W,     // [NB, IN, OUT]
                        const float* __restrict__ bias,  // [NB, OUT]
                        float*       __restrict__ out)   // [BT, OUT]
{
    extern __shared__ __align__(16) char dsm[];
    uint32_t*       xs_h  = (uint32_t*)(dsm + OFF_XH);
    uint32_t*       xs_l  = (uint32_t*)(dsm + OFF_XL);
    unsigned short* s_ent = (unsigned short*)(dsm + OFF_ENT);
    int*            s_cnt = (int*)(dsm + OFF_CNT);

    const int bank  = blockIdx.x;
    const int oBase = blockIdx.y * O_CHUNK;
    const int tid   = threadIdx.x;
    const int warp  = tid >> 5;
    const int lane  = tid & 31;
    const int gr    = lane >> 2;
    const int tg    = lane & 3;
    const int wcol  = warp * 16;

    char*  wring  = dsm + OFF_WS + warp * WRING_B;   // warp-private W ring
    float* wringf = (float*)wring;

    // L2 evict_last policy for the W stream (uniform, hoisted).
    uint64_t pol;
    asm("createpolicy.fractional.L2::evict_last.b64 %0, 1.0;" : "=l"(pol));

    if (tid == 0) *s_cnt = 0;
    __syncthreads();

    for (int e = tid; e < NENT; e += NTHR) {
        if (sel[e] == bank) {
            int pos = atomicAdd(s_cnt, 1);
            s_ent[pos] = (unsigned short)e;
        }
    }
    __syncthreads();
    const int count = *s_cnt;
    if (count == 0) return;

    // Warp's 16-col W slice base (rows = k).
    const float* Ww = W + (size_t)bank * IN_DIM * OUT_DIM + oBase + wcol;
    float2 bb[2];
    bb[0] = *(const float2*)(bias + (size_t)bank * OUT_DIM + oBase + wcol + tg * 2);
    bb[1] = *(const float2*)(bias + (size_t)bank * OUT_DIM + oBase + wcol + 8 + tg * 2);

    for (int tt = 0; tt < count; tt += MTOK) {
        // ── prologue: stages 0..2 into the warp-private ring ──
        #pragma unroll
        for (int s = 0; s < NSTAGE - 1; s++) {
            #pragma unroll
            for (int q = 0; q < 2; q++) {
                int idx = lane * 2 + q;
                int row = idx >> 2, c16 = idx & 3;
                cp_async16_l2(wring + s * WSTG_B + row * (WPITCH * 4) + c16 * 16,
                              Ww + (size_t)(s * 16 + row) * OUT_DIM + c16 * 4, pol);
            }
            CP_COMMIT();
        }

        // ── stage x cooperatively: prescale, bf16 hi/lo split, A-frag layout ──
        #pragma unroll
        for (int it = 0; it < 16; it++) {
            int j = tid + it * NTHR;      // 4096 = 32 slots x 128 k4-groups
            int t = j & 31;
            int q = j >> 5;
            int e = tt + t;
            float4 v = make_float4(0.f, 0.f, 0.f, 0.f);
            float  p = 0.f;
            if (e < count) {
                int ge = s_ent[e];
                p = prob[ge];
                v = *(const float4*)(x + (size_t)(ge >> 1) * IN_DIM + q * 4);
            }
            __nv_bfloat16 h0, l0, h1, l1, h2, l2, h3, l3;
            splitbf(v.x * p, h0, l0);
            splitbf(v.y * p, h1, l1);
            splitbf(v.z * p, h2, l2);
            splitbf(v.w * p, h3, l3);
            int trow = t & 15, mt = t >> 4;
            int grs = trow & 7, jb = trow >> 3;
            int ks = q >> 2;
            int kk = (q & 3) * 4;
            int tgA = (kk >> 1) & 3,       jA = jb + 2 * (kk >> 3);
            int tgB = ((kk + 2) >> 1) & 3, jB = jb + 2 * ((kk + 2) >> 3);
            int base = ks * 256 + mt * 128;
            int wA = base + (grs * 4 + tgA) * 4 + jA;
            int wB = base + (grs * 4 + tgB) * 4 + jB;
            xs_h[wA] = pack2(h0, h1);  xs_h[wB] = pack2(h2, h3);
            xs_l[wA] = pack2(l0, l1);  xs_l[wB] = pack2(l2, l3);
        }
        __syncthreads();   // xs visible to all warps; warps free-run from here

        float c[2][2][4];
        #pragma unroll
        for (int mt = 0; mt < 2; mt++)
            #pragma unroll
            for (int nt = 0; nt < 2; nt++)
                #pragma unroll
                for (int i = 0; i < 4; i++) c[mt][nt][i] = 0.f;

        // ── mainloop: NO barriers — per-warp ring, per-warp waits ──
        for (int ks = 0; ks < NKS; ks++) {
            int nks = ks + NSTAGE - 1;
            if (nks < NKS) {
                int slot = nks & (NSTAGE - 1);
                #pragma unroll
                for (int q = 0; q < 2; q++) {
                    int idx = lane * 2 + q;
                    int row = idx >> 2, c16 = idx & 3;
                    cp_async16_l2(wring + slot * WSTG_B + row * (WPITCH * 4) + c16 * 16,
                                  Ww + (size_t)(nks * 16 + row) * OUT_DIM + c16 * 4, pol);
                }
            }
            CP_COMMIT();
            CP_WAIT3();          // stage ks complete (warp-local)

            const float* wsf = wringf + (ks & (NSTAGE - 1)) * (16 * WPITCH);

            // B fragments: rows 2tg,2tg+1,2tg+8,2tg+9; cols nt*8+gr (warp-local)
            uint32_t bh[2][2], bl[2][2];
            #pragma unroll
            for (int nt = 0; nt < 2; nt++) {
                int cc = nt * 8 + gr;
                float w0 = wsf[(2 * tg) * WPITCH + cc];
                float w1 = wsf[(2 * tg + 1) * WPITCH + cc];
                float w2 = wsf[(2 * tg + 8) * WPITCH + cc];
                float w3 = wsf[(2 * tg + 9) * WPITCH + cc];
                __nv_bfloat16 h0, l0, h1, l1, h2, l2, h3, l3;
                splitbf(w0, h0, l0);
                splitbf(w1, h1, l1);
                splitbf(w2, h2, l2);
                splitbf(w3, h3, l3);
                bh[nt][0] = pack2(h0, h1);  bh[nt][1] = pack2(h2, h3);
                bl[nt][0] = pack2(l0, l1);  bl[nt][1] = pack2(l2, l3);
            }

            #pragma unroll
            for (int mt = 0; mt < 2; mt++) {
                uint32_t ah[4], al[4];
                *(uint4*)ah = *(const uint4*)&xs_h[ks * 256 + mt * 128 + lane * 4];
                *(uint4*)al = *(const uint4*)&xs_l[ks * 256 + mt * 128 + lane * 4];
                #pragma unroll
                for (int nt = 0; nt < 2; nt++) {
                    mma16(c[mt][nt], ah, bh[nt]);   // hi*hi
                    mma16(c[mt][nt], al, bh[nt]);   // lo*hi
                    mma16(c[mt][nt], ah, bl[nt]);   // hi*lo
                }
            }
        }
        CP_WAIT0();   // retire any stragglers before ring/xs reuse

        // ── epilogue: vector red (acc prob-prescaled; add p*bias) ──
        #pragma unroll
        for (int mt = 0; mt < 2; mt++) {
            #pragma unroll
            for (int nt = 0; nt < 2; nt++) {
                int colb = oBase + wcol + nt * 8 + tg * 2;
                int s0 = tt + mt * 16 + gr;
                if (s0 < count) {
                    int ge = s_ent[s0];
                    float p = prob[ge];
                    float* po = out + (size_t)(ge >> 1) * OUT_DIM + colb;
                    float v0 = c[mt][nt][0] + p * bb[nt].x;
                    float v1 = c[mt][nt][1] + p * bb[nt].y;
                    asm volatile("red.global.add.v2.f32 [%0], {%1, %2};"
                                 :: "l"(po), "f"(v0), "f"(v1) : "memory");
                }
                int s1 = tt + mt * 16 + gr + 8;
                if (s1 < count) {
                    int ge = s_ent[s1];
                    float p = prob[ge];
                    float* po = out + (size_t)(ge >> 1) * OUT_DIM + colb;
                    float v0 = c[mt][nt][2] + p * bb[nt].x;
                    float v1 = c[mt][nt][3] + p * bb[nt].y;
                    asm volatile("red.global.add.v2.f32 [%0], {%1, %2};"
                                 :: "l"(po), "f"(v0), "f"(v1) : "memory");
                }
            }
        }
        __syncthreads();   // xs reuse barrier (rare multi-tile case)
    }
}

extern "C" void kernel_launch(void* const* d_in, const int* in_sizes, int n_in,
                              void* d_out, int out_size) {
    const float* x    = (const float*)d_in[0];
    const int*   sel  = (const int*)  d_in[1];
    const float* prob = (const float*)d_in[2];
    const float* W    = (const float*)d_in[3];
    const float* bias = (const float*)d_in[4];
    float* out = (float*)d_out;

    cudaFuncSetAttribute(banked_linear_bf16,
                         cudaFuncAttributeMaxDynamicSharedMemorySize, SMEM_BYTES);

    int n4 = out_size / 4;
    zero_out_kernel<<<(n4 + 255) / 256, 256>>>((float4*)out, n4);

    dim3 grid(NB, O_SPLIT);
    banked_linear_bf16<<<grid, NTHR, SMEM_BYTES>>>(x, sel, prob, W, bias, out);
}

// round 15
// speedup vs baseline: 1.0524x; 1.0082x over previous
#include <cuda_runtime.h>
#include <cuda_bf16.h>
#include <cstdint>

// BankedLinear: B=2, T=256, K=2, IN=OUT=512, NB=64
#define NB       64
#define IN_DIM   512
#define OUT_DIM  512
#define KSEL     2
#define NENT     1024
#define O_SPLIT  4
#define O_CHUNK  128                 // outs per CTA (16 per warp)
#define NKS      32                  // k16-steps (full K=512)
#define MTOK     32                  // token tile: 2 m-tiles of 16
#define NTHR     256                 // 8 warps

// dynamic smem layout
#define OFF_XH   0                          // 32 KB: A-frag bf16x2 hi
#define OFF_XL   32768                      // 32 KB: A-frag bf16x2 lo
#define OFF_ENT  65536                      // 1024 u16
#define OFF_CNT  (OFF_ENT + 2048)           // 67584
#define SMEM_BYTES (OFF_CNT + 16)           // 67600

__global__ void zero_out_kernel(float4* __restrict__ out, int n4) {
    int i = blockIdx.x * blockDim.x + threadIdx.x;
    if (i < n4) out[i] = make_float4(0.f, 0.f, 0.f, 0.f);
}

__device__ __forceinline__ uint32_t pack2(__nv_bfloat16 lo, __nv_bfloat16 hi) {
    uint32_t u;
    asm("mov.b32 %0, {%1, %2};" : "=r"(u)
        : "h"(__bfloat16_as_ushort(lo)), "h"(__bfloat16_as_ushort(hi)));
    return u;
}
__device__ __forceinline__ void splitbf(float f, __nv_bfloat16& h, __nv_bfloat16& l) {
    h = __float2bfloat16_rn(f);
    l = __float2bfloat16_rn(f - __bfloat162float(h));
}
// packed split: (f0,f1) -> hi bf16x2 (lo half=f0), lo-residual bf16x2
__device__ __forceinline__ uint32_t cvt2(float hi, float lo) {
    uint32_t r;
    asm("cvt.rn.bf16x2.f32 %0, %1, %2;" : "=r"(r) : "f"(hi), "f"(lo));
    return r;
}
__device__ __forceinline__ void split_pair(float f0, float f1,
                                           uint32_t& h, uint32_t& l) {
    h = cvt2(f1, f0);
    float h0 = __uint_as_float(h << 16);
    float h1 = __uint_as_float(h & 0xFFFF0000u);
    l = cvt2(f1 - h1, f0 - h0);
}
__device__ __forceinline__ void mma16(float* c, const uint32_t* a, const uint32_t* b) {
    asm volatile(
        "mma.sync.aligned.m16n8k16.row.col.f32.bf16.bf16.f32 "
        "{%0,%1,%2,%3}, {%4,%5,%6,%7}, {%8,%9}, {%0,%1,%2,%3};"
        : "+f"(c[0]), "+f"(c[1]), "+f"(c[2]), "+f"(c[3])
        : "r"(a[0]), "r"(a[1]), "r"(a[2]), "r"(a[3]), "r"(b[0]), "r"(b[1]));
}

// 8 B-fragment LDG.32s for one kstep (rows 2tg,2tg+1,2tg+8,2tg+9; cols gr, 8+gr)
#define LOADW(dst, base) do {                         \
    (dst)[0] = (base)[0];                             \
    (dst)[1] = (base)[OUT_DIM];                       \
    (dst)[2] = (base)[8 * OUT_DIM];                   \
    (dst)[3] = (base)[9 * OUT_DIM];                   \
    (dst)[4] = (base)[8];                             \
    (dst)[5] = (base)[OUT_DIM + 8];                   \
    (dst)[6] = (base)[8 * OUT_DIM + 8];               \
    (dst)[7] = (base)[9 * OUT_DIM + 8];               \
} while (0)

__global__ __launch_bounds__(NTHR, 2)
void banked_linear_bf16(const float* __restrict__ x,     // [BT, IN]
                        const int*   __restrict__ sel,   // [BT, K]
                        const float* __restrict__ prob,  // [BT, K]
                        const float* __restrict__ W,     // [NB, IN, OUT]
                        const float* __restrict__ bias,  // [NB, OUT]
                        float*       __restrict__ out)   // [BT, OUT]
{
    extern __shared__ __align__(16) char dsm[];
    uint32_t*       xs_h  = (uint32_t*)(dsm + OFF_XH);
    uint32_t*       xs_l  = (uint32_t*)(dsm + OFF_XL);
    unsigned short* s_ent = (unsigned short*)(dsm + OFF_ENT);
    int*            s_cnt = (int*)(dsm + OFF_CNT);

    const int bank  = blockIdx.x;
    const int oBase = blockIdx.y * O_CHUNK;
    const int tid   = threadIdx.x;
    const int warp  = tid >> 5;
    const int lane  = tid & 31;
    const int gr    = lane >> 2;
    const int tg    = lane & 3;
    const int wcol  = warp * 16;

    if (tid == 0) *s_cnt = 0;
    __syncthreads();

    for (int e = tid; e < NENT; e += NTHR) {
        if (sel[e] == bank) {
            int pos = atomicAdd(s_cnt, 1);
            s_ent[pos] = (unsigned short)e;
        }
    }
    __syncthreads();
    const int count = *s_cnt;
    if (count == 0) return;

    // Per-lane B-fragment base: W[row=2tg][col=oBase+wcol+gr] of this bank.
    const float* Wl = W + (size_t)bank * IN_DIM * OUT_DIM
                        + (size_t)(2 * tg) * OUT_DIM + oBase + wcol + gr;
    float2 bb[2];
    bb[0] = *(const float2*)(bias + (size_t)bank * OUT_DIM + oBase + wcol + tg * 2);
    bb[1] = *(const float2*)(bias + (size_t)bank * OUT_DIM + oBase + wcol + 8 + tg * 2);

    for (int tt = 0; tt < count; tt += MTOK) {
        // ── stage x cooperatively: prescale, bf16 hi/lo split, A-frag layout ──
        #pragma unroll
        for (int it = 0; it < 16; it++) {
            int j = tid + it * NTHR;      // 4096 = 32 slots x 128 k4-groups
            int t = j & 31;
            int q = j >> 5;
            int e = tt + t;
            float4 v = make_float4(0.f, 0.f, 0.f, 0.f);
            float  p = 0.f;
            if (e < count) {
                int ge = s_ent[e];
                p = prob[ge];
                v = *(const float4*)(x + (size_t)(ge >> 1) * IN_DIM + q * 4);
            }
            uint32_t hA, lA, hB, lB;
            split_pair(v.x * p, v.y * p, hA, lA);
            split_pair(v.z * p, v.w * p, hB, lB);
            int trow = t & 15, mt = t >> 4;
            int grs = trow & 7, jb = trow >> 3;
            int ks = q >> 2;
            int kk = (q & 3) * 4;
            int tgA = (kk >> 1) & 3,       jA = jb + 2 * (kk >> 3);
            int tgB = ((kk + 2) >> 1) & 3, jB = jb + 2 * ((kk + 2) >> 3);
            int base = ks * 256 + mt * 128;
            int wA = base + (grs * 4 + tgA) * 4 + jA;
            int wB = base + (grs * 4 + tgB) * 4 + jB;
            xs_h[wA] = hA;  xs_h[wB] = hB;
            xs_l[wA] = lA;  xs_l[wB] = lB;
        }

        // ── prologue: W register ring slots 0,1 (ksteps 0,1) ──
        float wr[4][8];
        LOADW(wr[0], Wl);
        LOADW(wr[1], Wl + 16 * OUT_DIM);

        __syncthreads();   // xs visible; warps free-run from here

        float c[2][2][4];
        #pragma unroll
        for (int mt = 0; mt < 2; mt++)
            #pragma unroll
            for (int nt = 0; nt < 2; nt++)
                #pragma unroll
                for (int i = 0; i < 4; i++) c[mt][nt][i] = 0.f;

        // ── mainloop: barrier-free; W direct LDG, 2-kstep prefetch distance ──
        #pragma unroll 4
        for (int ks = 0; ks < NKS; ks++) {
            if (ks + 2 < NKS)
                LOADW(wr[(ks + 2) & 3], Wl + (size_t)(ks + 2) * 16 * OUT_DIM);

            const float* wc = wr[ks & 3];
            uint32_t bh[2][2], bl[2][2];
            split_pair(wc[0], wc[1], bh[0][0], bl[0][0]);
            split_pair(wc[2], wc[3], bh[0][1], bl[0][1]);
            split_pair(wc[4], wc[5], bh[1][0], bl[1][0]);
            split_pair(wc[6], wc[7], bh[1][1], bl[1][1]);

            #pragma unroll
            for (int mt = 0; mt < 2; mt++) {
                uint32_t ah[4], al[4];
                *(uint4*)ah = *(const uint4*)&xs_h[ks * 256 + mt * 128 + lane * 4];
                *(uint4*)al = *(const uint4*)&xs_l[ks * 256 + mt * 128 + lane * 4];
                #pragma unroll
                for (int nt = 0; nt < 2; nt++) {
                    mma16(c[mt][nt], ah, bh[nt]);   // hi*hi
                    mma16(c[mt][nt], al, bh[nt]);   // lo*hi
                    mma16(c[mt][nt], ah, bl[nt]);   // hi*lo
                }
            }
        }

        // ── epilogue: vector red (acc prob-prescaled; add p*bias) ──
        #pragma unroll
        for (int mt = 0; mt < 2; mt++) {
            #pragma unroll
            for (int nt = 0; nt < 2; nt++) {
                int colb = oBase + wcol + nt * 8 + tg * 2;
                int s0 = tt + mt * 16 + gr;
                if (s0 < count) {
                    int ge = s_ent[s0];
                    float p = prob[ge];
                    float* po = out + (size_t)(ge >> 1) * OUT_DIM + colb;
                    float v0 = c[mt][nt][0] + p * bb[nt].x;
                    float v1 = c[mt][nt][1] + p * bb[nt].y;
                    asm volatile("red.global.add.v2.f32 [%0], {%1, %2};"
                                 :: "l"(po), "f"(v0), "f"(v1) : "memory");
                }
                int s1 = tt + mt * 16 + gr + 8;
                if (s1 < count) {
                    int ge = s_ent[s1];
                    float p = prob[ge];
                    float* po = out + (size_t)(ge >> 1) * OUT_DIM + colb;
                    float v0 = c[mt][nt][2] + p * bb[nt].x;
                    float v1 = c[mt][nt][3] + p * bb[nt].y;
                    asm volatile("red.global.add.v2.f32 [%0], {%1, %2};"
                                 :: "l"(po), "f"(v0), "f"(v1) : "memory");
                }
            }
        }
        __syncthreads();   // xs reuse barrier (rare multi-tile case)
    }
}

extern "C" void kernel_launch(void* const* d_in, const int* in_sizes, int n_in,
                              void* d_out, int out_size) {
    const float* x    = (const float*)d_in[0];
    const int*   sel  = (const int*)  d_in[1];
    const float* prob = (const float*)d_in[2];
    const float* W    = (const float*)d_in[3];
    const float* bias = (const float*)d_in[4];
    float* out = (float*)d_out;

    cudaFuncSetAttribute(banked_linear_bf16,
                         cudaFuncAttributeMaxDynamicSharedMemorySize, SMEM_BYTES);

    int n4 = out_size / 4;
    zero_out_kernel<<<(n4 + 255) / 256, 256>>>((float4*)out, n4);

    dim3 grid(NB, O_SPLIT);
    banked_linear_bf16<<<grid, NTHR, SMEM_BYTES>>>(x, sel, prob, W, bias, out);
}

// round 16
// speedup vs baseline: 1.2176x; 1.1570x over previous
#include <cuda_runtime.h>
#include <cuda_bf16.h>
#include <cstdint>

// BankedLinear: B=2, T=256, K=2, IN=OUT=512, NB=64
#define NB       64
#define IN_DIM   512
#define OUT_DIM  512
#define KSEL     2
#define NENT     1024
#define O_SPLIT  4
#define O_CHUNK  128                 // outs per CTA (16 per warp)
#define NKS      32                  // k16-steps (full K=512)
#define MTOK     32                  // token tile: 2 m-tiles of 16
#define NTHR     256                 // 8 warps
#define NSTAGE   4                   // per-warp W ring depth
#define WPITCH   20                  // floats per W row (bank-conflict-free)
#define WSTG_B   (16 * WPITCH * 4)   // 1280 B per stage per warp
#define WRING_B  (NSTAGE * WSTG_B)   // 5120 B per warp

// dynamic smem layout
#define OFF_XH   0                          // 32 KB: A-frag bf16x2 hi
#define OFF_XL   32768                      // 32 KB: A-frag bf16x2 lo
#define OFF_WS   65536                      // 8 warps x 5120 = 40960
#define OFF_ENT  (OFF_WS + 8 * WRING_B)     // 106496: 1024 u16
#define OFF_CNT  (OFF_ENT + 2048)           // 108544
#define SMEM_BYTES (OFF_CNT + 16)           // 108560

__global__ void zero_out_kernel(float4* __restrict__ out, int n4) {
    int i = blockIdx.x * blockDim.x + threadIdx.x;
    if (i < n4) out[i] = make_float4(0.f, 0.f, 0.f, 0.f);
}

__device__ __forceinline__ void cp_async16(void* dst, const void* src) {
    unsigned d = (unsigned)__cvta_generic_to_shared(dst);
    asm volatile("cp.async.cg.shared.global [%0], [%1], 16;\n" :: "r"(d), "l"(src));
}
#define CP_COMMIT() asm volatile("cp.async.commit_group;\n" ::)
#define CP_WAIT3()  asm volatile("cp.async.wait_group 3;\n" ::)
#define CP_WAIT0()  asm volatile("cp.async.wait_group 0;\n" ::)

__device__ __forceinline__ uint32_t cvt2(float hi, float lo) {
    uint32_t r;
    asm("cvt.rn.bf16x2.f32 %0, %1, %2;" : "=r"(r) : "f"(hi), "f"(lo));
    return r;
}
// split a float pair into hi/lo bf16x2 regs (packed cvt, 6 ops)
__device__ __forceinline__ void split_pair(float f0, float f1,
                                           uint32_t& h, uint32_t& l) {
    h = cvt2(f1, f0);
    float h0 = __uint_as_float(h << 16);
    float h1 = __uint_as_float(h & 0xFFFF0000u);
    l = cvt2(f1 - h1, f0 - h0);
}
__device__ __forceinline__ void mma16(float* c, const uint32_t* a, const uint32_t* b) {
    asm volatile(
        "mma.sync.aligned.m16n8k16.row.col.f32.bf16.bf16.f32 "
        "{%0,%1,%2,%3}, {%4,%5,%6,%7}, {%8,%9}, {%0,%1,%2,%3};"
        : "+f"(c[0]), "+f"(c[1]), "+f"(c[2]), "+f"(c[3])
        : "r"(a[0]), "r"(a[1]), "r"(a[2]), "r"(a[3]), "r"(b[0]), "r"(b[1]));
}

__global__ __launch_bounds__(NTHR, 2)
void banked_linear_bf16(const float* __restrict__ x,     // [BT, IN]
                        const int*   __restrict__ sel,   // [BT, K]
                        const float* __restrict__ prob,  // [BT, K]
                        const float* __restrict__ W,     // [NB, IN, OUT]
                        const float* __restrict__ bias,  // [NB, OUT]
                        float*       __restrict__ out)   // [BT, OUT]
{
    extern __shared__ __align__(16) char dsm[];
    uint32_t*       xs_h  = (uint32_t*)(dsm + OFF_XH);
    uint32_t*       xs_l  = (uint32_t*)(dsm + OFF_XL);
    unsigned short* s_ent = (unsigned short*)(dsm + OFF_ENT);
    int*            s_cnt = (int*)(dsm + OFF_CNT);

    const int bank  = blockIdx.x;
    const int oBase = blockIdx.y * O_CHUNK;
    const int tid   = threadIdx.x;
    const int warp  = tid >> 5;
    const int lane  = tid & 31;
    const int gr    = lane >> 2;
    const int tg    = lane & 3;
    const int wcol  = warp * 16;

    char*  wring  = dsm + OFF_WS + warp * WRING_B;   // warp-private W ring
    float* wringf = (float*)wring;

    if (tid == 0) *s_cnt = 0;
    __syncthreads();

    for (int e = tid; e < NENT; e += NTHR) {
        if (sel[e] == bank) {
            int pos = atomicAdd(s_cnt, 1);
            s_ent[pos] = (unsigned short)e;
        }
    }
    __syncthreads();
    const int count = *s_cnt;
    if (count == 0) return;

    // Warp's 16-col W slice base (rows = k).
    const float* Ww = W + (size_t)bank * IN_DIM * OUT_DIM + oBase + wcol;
    float2 bb[2];
    bb[0] = *(const float2*)(bias + (size_t)bank * OUT_DIM + oBase + wcol + tg * 2);
    bb[1] = *(const float2*)(bias + (size_t)bank * OUT_DIM + oBase + wcol + 8 + tg * 2);

    for (int tt = 0; tt < count; tt += MTOK) {
        // ── prologue: stages 0..2 into the warp-private ring (row-major fill) ──
        #pragma unroll
        for (int s = 0; s < NSTAGE - 1; s++) {
            #pragma unroll
            for (int q = 0; q < 2; q++) {
                int idx = q * 32 + lane;           // lanes cover whole 64B rows
                int row = idx >> 2, c16 = idx & 3;
                cp_async16(wring + s * WSTG_B + row * (WPITCH * 4) + c16 * 16,
                           Ww + (size_t)(s * 16 + row) * OUT_DIM + c16 * 4);
            }
            CP_COMMIT();
        }

        // ── stage x: TOKEN-MAJOR mapping — warp reads one token's contiguous 512B ──
        #pragma unroll
        for (int it = 0; it < 16; it++) {
            int j = tid + it * NTHR;      // 4096 = 32 tokens x 128 k4-groups
            int t = j >> 7;               // token slot (uniform per warp)
            int q = j & 127;              // k4-group (consecutive per lane)
            int e = tt + t;
            float4 v = make_float4(0.f, 0.f, 0.f, 0.f);
            float  p = 0.f;
            if (e < count) {
                int ge = s_ent[e];        // LDS broadcast
                p = prob[ge];             // gmem broadcast (1 sector)
                v = *(const float4*)(x + (size_t)(ge >> 1) * IN_DIM + q * 4);
            }
            uint32_t hA, lA, hB, lB;
            split_pair(v.x * p, v.y * p, hA, lA);
            split_pair(v.z * p, v.w * p, hB, lB);
            int trow = t & 15, mt = t >> 4;
            int grs = trow & 7, jb = trow >> 3;
            int ks = q >> 2;
            int kk = (q & 3) * 4;
            int tgA = (kk >> 1) & 3,       jA = jb + 2 * (kk >> 3);
            int tgB = ((kk + 2) >> 1) & 3, jB = jb + 2 * ((kk + 2) >> 3);
            int base = ks * 256 + mt * 128;
            int wA = base + (grs * 4 + tgA) * 4 + jA;
            int wB = base + (grs * 4 + tgB) * 4 + jB;
            xs_h[wA] = hA;  xs_h[wB] = hB;
            xs_l[wA] = lA;  xs_l[wB] = lB;
        }
        __syncthreads();   // xs visible to all warps; warps free-run from here

        float c[2][2][4];
        #pragma unroll
        for (int mt = 0; mt < 2; mt++)
            #pragma unroll
            for (int nt = 0; nt < 2; nt++)
                #pragma unroll
                for (int i = 0; i < 4; i++) c[mt][nt][i] = 0.f;

        // ── mainloop: NO barriers — per-warp ring, per-warp waits ──
        for (int ks = 0; ks < NKS; ks++) {
            int nks = ks + NSTAGE - 1;
            if (nks < NKS) {
                int slot = nks & (NSTAGE - 1);
                #pragma unroll
                for (int q = 0; q < 2; q++) {
                    int idx = q * 32 + lane;       // row-major fill
                    int row = idx >> 2, c16 = idx & 3;
                    cp_async16(wring + slot * WSTG_B + row * (WPITCH * 4) + c16 * 16,
                               Ww + (size_t)(nks * 16 + row) * OUT_DIM + c16 * 4);
                }
            }
            CP_COMMIT();
            CP_WAIT3();          // stage ks complete (warp-local)

            const float* wsf = wringf + (ks & (NSTAGE - 1)) * (16 * WPITCH);

            // B fragments: rows 2tg,2tg+1,2tg+8,2tg+9; cols nt*8+gr (conflict-free)
            uint32_t bh[2][2], bl[2][2];
            #pragma unroll
            for (int nt = 0; nt < 2; nt++) {
                int cc = nt * 8 + gr;
                float w0 = wsf[(2 * tg) * WPITCH + cc];
                float w1 = wsf[(2 * tg + 1) * WPITCH + cc];
                float w2 = wsf[(2 * tg + 8) * WPITCH + cc];
                float w3 = wsf[(2 * tg + 9) * WPITCH + cc];
                split_pair(w0, w1, bh[nt][0], bl[nt][0]);
                split_pair(w2, w3, bh[nt][1], bl[nt][1]);
            }

            #pragma unroll
            for (int mt = 0; mt < 2; mt++) {
                uint32_t ah[4], al[4];
                *(uint4*)ah = *(const uint4*)&xs_h[ks * 256 + mt * 128 + lane * 4];
                *(uint4*)al = *(const uint4*)&xs_l[ks * 256 + mt * 128 + lane * 4];
                #pragma unroll
                for (int nt = 0; nt < 2; nt++) {
                    mma16(c[mt][nt], ah, bh[nt]);   // hi*hi
                    mma16(c[mt][nt], al, bh[nt]);   // lo*hi
                    mma16(c[mt][nt], ah, bl[nt]);   // hi*lo
                }
            }
        }
        CP_WAIT0();   // retire any stragglers before ring/xs reuse

        // ── epilogue: vector red (acc prob-prescaled; add p*bias) ──
        #pragma unroll
        for (int mt = 0; mt < 2; mt++) {
            #pragma unroll
            for (int nt = 0; nt < 2; nt++) {
                int colb = oBase + wcol + nt * 8 + tg * 2;
                int s0 = tt + mt * 16 + gr;
                if (s0 < count) {
                    int ge = s_ent[s0];
                    float p = prob[ge];
                    float* po = out + (size_t)(ge >> 1) * OUT_DIM + colb;
                    float v0 = c[mt][nt][0] + p * bb[nt].x;
                    float v1 = c[mt][nt][1] + p * bb[nt].y;
                    asm volatile("red.global.add.v2.f32 [%0], {%1, %2};"
                                 :: "l"(po), "f"(v0), "f"(v1) : "memory");
                }
                int s1 = tt + mt * 16 + gr + 8;
                if (s1 < count) {
                    int ge = s_ent[s1];
                    float p = prob[ge];
                    float* po = out + (size_t)(ge >> 1) * OUT_DIM + colb;
                    float v0 = c[mt][nt][2] + p * bb[nt].x;
                    float v1 = c[mt][nt][3] + p * bb[nt].y;
                    asm volatile("red.global.add.v2.f32 [%0], {%1, %2};"
                                 :: "l"(po), "f"(v0), "f"(v1) : "memory");
                }
            }
        }
        __syncthreads();   // xs reuse barrier (rare multi-tile case)
    }
}

extern "C" void kernel_launch(void* const* d_in, const int* in_sizes, int n_in,
                              void* d_out, int out_size) {
    const float* x    = (const float*)d_in[0];
    const int*   sel  = (const int*)  d_in[1];
    const float* prob = (const float*)d_in[2];
    const float* W    = (const float*)d_in[3];
    const float* bias = (const float*)d_in[4];
    float* out = (float*)d_out;

    cudaFuncSetAttribute(banked_linear_bf16,
                         cudaFuncAttributeMaxDynamicSharedMemorySize, SMEM_BYTES);

    int n4 = out_size / 4;
    zero_out_kernel<<<(n4 + 255) / 256, 256>>>((float4*)out, n4);

    dim3 grid(NB, O_SPLIT);
    banked_linear_bf16<<<grid, NTHR, SMEM_BYTES>>>(x, sel, prob, W, bias, out);
}

// round 17
// speedup vs baseline: 1.3316x; 1.0936x over previous
#include <cuda_runtime.h>
#include <cuda_bf16.h>
#include <cstdint>

// BankedLinear: B=2, T=256, K=2, IN=OUT=512, NB=64
#define NB       64
#define IN_DIM   512
#define OUT_DIM  512
#define KSEL     2
#define NENT     1024
#define O_SPLIT  4
#define O_CHUNK  128                 // outs per CTA (16 per warp)
#define NKS      32                  // k16-steps (full K=512)
#define MTOK     32                  // token tile: 2 m-tiles of 16
#define NTHR     256                 // 8 warps
#define NSTAGE   4                   // per-warp W ring depth
#define WPITCH   20                  // floats per W row (bank-conflict-free: 2*20 ≡ 8 mod 32)
#define WSTG_B   (16 * WPITCH * 4)   // 1280 B per stage per warp
#define WRING_B  (NSTAGE * WSTG_B)   // 5120 B per warp

// dynamic smem layout
#define OFF_XH   0                          // 32 KB: A-frag bf16x2 hi
#define OFF_XL   32768                      // 32 KB: A-frag bf16x2 lo
#define OFF_WS   65536                      // 8 warps x 5120 = 40960
#define OFF_ENT  (OFF_WS + 8 * WRING_B)     // 106496: 1024 u16
#define OFF_CNT  (OFF_ENT + 2048)           // 108544
#define SMEM_BYTES (OFF_CNT + 16)           // 108560

__global__ void zero_out_kernel(float4* __restrict__ out, int n4) {
    int i = blockIdx.x * blockDim.x + threadIdx.x;
    if (i < n4) out[i] = make_float4(0.f, 0.f, 0.f, 0.f);
}

__device__ __forceinline__ void cp_async16(void* dst, const void* src) {
    unsigned d = (unsigned)__cvta_generic_to_shared(dst);
    asm volatile("cp.async.cg.shared.global [%0], [%1], 16;\n" :: "r"(d), "l"(src));
}
#define CP_COMMIT() asm volatile("cp.async.commit_group;\n" ::)
#define CP_WAIT2()  asm volatile("cp.async.wait_group 2;\n" ::)
#define CP_WAIT0()  asm volatile("cp.async.wait_group 0;\n" ::)

__device__ __forceinline__ uint32_t cvt2(float hi, float lo) {
    uint32_t r;
    asm("cvt.rn.bf16x2.f32 %0, %1, %2;" : "=r"(r) : "f"(hi), "f"(lo));
    return r;
}
// split a float pair into hi/lo bf16x2 regs (packed cvt, 6 ops)
__device__ __forceinline__ void split_pair(float f0, float f1,
                                           uint32_t& h, uint32_t& l) {
    h = cvt2(f1, f0);
    float h0 = __uint_as_float(h << 16);
    float h1 = __uint_as_float(h & 0xFFFF0000u);
    l = cvt2(f1 - h1, f0 - h0);
}
__device__ __forceinline__ void mma16(float* c, const uint32_t* a, const uint32_t* b) {
    asm volatile(
        "mma.sync.aligned.m16n8k16.row.col.f32.bf16.bf16.f32 "
        "{%0,%1,%2,%3}, {%4,%5,%6,%7}, {%8,%9}, {%0,%1,%2,%3};"
        : "+f"(c[0]), "+f"(c[1]), "+f"(c[2]), "+f"(c[3])
        : "r"(a[0]), "r"(a[1]), "r"(a[2]), "r"(a[3]), "r"(b[0]), "r"(b[1]));
}

// Load + split one stage's B fragments (8 conflict-free scalar LDS + 12 alu).
__device__ __forceinline__ void load_bfrags(uint32_t bh[2][2], uint32_t bl[2][2],
                                            const float* wsf, int gr, int tg) {
    #pragma unroll
    for (int nt = 0; nt < 2; nt++) {
        int cc = nt * 8 + gr;
        float w0 = wsf[(2 * tg) * WPITCH + cc];
        float w1 = wsf[(2 * tg + 1) * WPITCH + cc];
        float w2 = wsf[(2 * tg + 8) * WPITCH + cc];
        float w3 = wsf[(2 * tg + 9) * WPITCH + cc];
        split_pair(w0, w1, bh[nt][0], bl[nt][0]);
        split_pair(w2, w3, bh[nt][1], bl[nt][1]);
    }
}

__global__ __launch_bounds__(NTHR, 2)
void banked_linear_bf16(const float* __restrict__ x,     // [BT, IN]
                        const int*   __restrict__ sel,   // [BT, K]
                        const float* __restrict__ prob,  // [BT, K]
                        const float* __restrict__ W,     // [NB, IN, OUT]
                        const float* __restrict__ bias,  // [NB, OUT]
                        float*       __restrict__ out)   // [BT, OUT]
{
    extern __shared__ __align__(16) char dsm[];
    uint32_t*       xs_h  = (uint32_t*)(dsm + OFF_XH);
    uint32_t*       xs_l  = (uint32_t*)(dsm + OFF_XL);
    unsigned short* s_ent = (unsigned short*)(dsm + OFF_ENT);
    int*            s_cnt = (int*)(dsm + OFF_CNT);

    const int bank  = blockIdx.x;
    const int oBase = blockIdx.y * O_CHUNK;
    const int tid   = threadIdx.x;
    const int warp  = tid >> 5;
    const int lane  = tid & 31;
    const int gr    = lane >> 2;
    const int tg    = lane & 3;
    const int wcol  = warp * 16;

    char*  wring  = dsm + OFF_WS + warp * WRING_B;   // warp-private W ring
    float* wringf = (float*)wring;

    if (tid == 0) *s_cnt = 0;
    __syncthreads();

    for (int e = tid; e < NENT; e += NTHR) {
        if (sel[e] == bank) {
            int pos = atomicAdd(s_cnt, 1);
            s_ent[pos] = (unsigned short)e;
        }
    }
    __syncthreads();
    const int count = *s_cnt;
    if (count == 0) return;

    // Warp's 16-col W slice base (rows = k).
    const float* Ww = W + (size_t)bank * IN_DIM * OUT_DIM + oBase + wcol;
    float2 bb[2];
    bb[0] = *(const float2*)(bias + (size_t)bank * OUT_DIM + oBase + wcol + tg * 2);
    bb[1] = *(const float2*)(bias + (size_t)bank * OUT_DIM + oBase + wcol + 8 + tg * 2);

    for (int tt = 0; tt < count; tt += MTOK) {
        // ── prologue: stages 0..2 into the warp-private ring (row-major fill) ──
        #pragma unroll
        for (int s = 0; s < NSTAGE - 1; s++) {
            #pragma unroll
            for (int q = 0; q < 2; q++) {
                int idx = q * 32 + lane;           // lanes cover whole 64B rows
                int row = idx >> 2, c16 = idx & 3;
                cp_async16(wring + s * WSTG_B + row * (WPITCH * 4) + c16 * 16,
                           Ww + (size_t)(s * 16 + row) * OUT_DIM + c16 * 4);
            }
            CP_COMMIT();
        }

        // ── stage x: token-major reads; XOR-swizzled A-frag stores (conflict-free) ──
        #pragma unroll
        for (int it = 0; it < 16; it++) {
            int j = tid + it * NTHR;      // 4096 = 32 tokens x 128 k4-groups
            int t = j >> 7;               // token slot (uniform per warp)
            int q = j & 127;              // k4-group (consecutive per lane)
            int e = tt + t;
            float4 v = make_float4(0.f, 0.f, 0.f, 0.f);
            float  p = 0.f;
            if (e < count) {
                int ge = s_ent[e];        // LDS broadcast
                p = prob[ge];             // gmem broadcast
                v = *(const float4*)(x + (size_t)(ge >> 1) * IN_DIM + q * 4);
            }
            uint32_t hA, lA, hB, lB;
            split_pair(v.x * p, v.y * p, hA, lA);
            split_pair(v.z * p, v.w * p, hB, lB);
            int trow = t & 15, mt = t >> 4;
            int grs = trow & 7, jb = trow >> 3;
            int ks = q >> 2;
            int kk = (q & 3) * 4;
            int tgA = (kk >> 1) & 3,       jA = jb + 2 * (kk >> 3);
            int tgB = ((kk + 2) >> 1) & 3, jB = jb + 2 * ((kk + 2) >> 3);
            int base = ks * 256 + mt * 128;
            int xr = (ks & 3) * 8;                       // bank swizzle (bits 3,4)
            int wA = (base + (grs * 4 + tgA) * 4 + jA) ^ xr;
            int wB = (base + (grs * 4 + tgB) * 4 + jB) ^ xr;
            xs_h[wA] = hA;  xs_h[wB] = hB;
            xs_l[wA] = lA;  xs_l[wB] = lB;
        }
        __syncthreads();   // xs visible to all warps; warps free-run from here

        float c[2][2][4];
        #pragma unroll
        for (int mt = 0; mt < 2; mt++)
            #pragma unroll
            for (int nt = 0; nt < 2; nt++)
                #pragma unroll
                for (int i = 0; i < 4; i++) c[mt][nt][i] = 0.f;

        // ── preload B fragments for stage 0 (3 groups committed; wait ≤2 → stage 0 done) ──
        uint32_t bh[2][2][2], bl[2][2][2];   // [buf][nt][reg]
        CP_WAIT2();
        load_bfrags(bh[0], bl[0], wringf, gr, tg);

        // ── mainloop: barrier-free; B-frag double buffer hides LDS+split ──
        #pragma unroll 4
        for (int ks = 0; ks < NKS; ks++) {
            const int cur = ks & 1, nxt = cur ^ 1;

            int nks = ks + NSTAGE - 1;
            if (nks < NKS) {
                int slot = nks & (NSTAGE - 1);
                #pragma unroll
                for (int q = 0; q < 2; q++) {
                    int idx = q * 32 + lane;       // row-major fill
                    int row = idx >> 2, c16 = idx & 3;
                    cp_async16(wring + slot * WSTG_B + row * (WPITCH * 4) + c16 * 16,
                               Ww + (size_t)(nks * 16 + row) * OUT_DIM + c16 * 4);
                }
            }
            CP_COMMIT();         // commit even when empty: keeps group counts aligned

            if (ks + 1 < NKS) {
                CP_WAIT2();      // stage ks+1 complete (warp-local)
                load_bfrags(bh[nxt], bl[nxt],
                            wringf + ((ks + 1) & (NSTAGE - 1)) * (16 * WPITCH), gr, tg);
            }

            const int xr = (ks & 3) * 8;
            #pragma unroll
            for (int mt = 0; mt < 2; mt++) {
                uint32_t ah[4], al[4];
                *(uint4*)ah = *(const uint4*)&xs_h[ks * 256 + mt * 128 + ((lane * 4) ^ xr)];
                *(uint4*)al = *(const uint4*)&xs_l[ks * 256 + mt * 128 + ((lane * 4) ^ xr)];
                #pragma unroll
                for (int nt = 0; nt < 2; nt++) {
                    mma16(c[mt][nt], ah, bh[cur][nt]);   // hi*hi
                    mma16(c[mt][nt], al, bh[cur][nt]);   // lo*hi
                    mma16(c[mt][nt], ah, bl[cur][nt]);   // hi*lo
                }
            }
        }
        CP_WAIT0();   // retire any stragglers before ring/xs reuse

        // ── epilogue: vector red (acc prob-prescaled; add p*bias) ──
        #pragma unroll
        for (int mt = 0; mt < 2; mt++) {
            #pragma unroll
            for (int nt = 0; nt < 2; nt++) {
                int colb = oBase + wcol + nt * 8 + tg * 2;
                int s0 = tt + mt * 16 + gr;
                if (s0 < count) {
                    int ge = s_ent[s0];
                    float p = prob[ge];
                    float* po = out + (size_t)(ge >> 1) * OUT_DIM + colb;
                    float v0 = c[mt][nt][0] + p * bb[nt].x;
                    float v1 = c[mt][nt][1] + p * bb[nt].y;
                    asm volatile("red.global.add.v2.f32 [%0], {%1, %2};"
                                 :: "l"(po), "f"(v0), "f"(v1) : "memory");
                }
                int s1 = tt + mt * 16 + gr + 8;
                if (s1 < count) {
                    int ge = s_ent[s1];
                    float p = prob[ge];
                    float* po = out + (size_t)(ge >> 1) * OUT_DIM + colb;
                    float v0 = c[mt][nt][2] + p * bb[nt].x;
                    float v1 = c[mt][nt][3] + p * bb[nt].y;
                    asm volatile("red.global.add.v2.f32 [%0], {%1, %2};"
                                 :: "l"(po), "f"(v0), "f"(v1) : "memory");
                }
            }
        }
        __syncthreads();   // xs reuse barrier (rare multi-tile case)
    }
}

extern "C" void kernel_launch(void* const* d_in, const int* in_sizes, int n_in,
                              void* d_out, int out_size) {
    const float* x    = (const float*)d_in[0];
    const int*   sel  = (const int*)  d_in[1];
    const float* prob = (const float*)d_in[2];
    const float* W    = (const float*)d_in[3];
    const float* bias = (const float*)d_in[4];
    float* out = (float*)d_out;

    cudaFuncSetAttribute(banked_linear_bf16,
                         cudaFuncAttributeMaxDynamicSharedMemorySize, SMEM_BYTES);

    int n4 = out_size / 4;
    zero_out_kernel<<<(n4 + 255) / 256, 256>>>((float4*)out, n4);

    dim3 grid(NB, O_SPLIT);
    banked_linear_bf16<<<grid, NTHR, SMEM_BYTES>>>(x, sel, prob, W, bias, out);
}